// round 8
// baseline (speedup 1.0000x reference)
#include <cuda_runtime.h>
#include <math.h>

// Problem shape (fixed by dataset)
#define QN 8192   // queries
#define KN 1024   // prototypes
#define DN 1024   // feature dim
#define EPSF 1e-6f

// GEMM tiling
#define BM 128
#define BN 128
#define BK 16
#define NCT (KN / BN)   // 8 column tiles

// ---- allocation-free scratch (device globals) ----
__device__ float g_qsq[QN];
__device__ float g_qsum[QN];
__device__ float g_psq[KN];
__device__ float g_psum[KN];
__device__ float g_Spart[QN * NCT];   // per (row, colTile) partial sum of u
__device__ float g_Upart[QN * NCT];   // per (row, colTile) partial sum of u*dist
__device__ float g_Mpart[QN * NCT];   // per (row, colTile) partial max of u

// ============================================================
// 1) Row stats: one warp per row. Rows [0,QN) -> Q, [QN,QN+KN) -> P
// ============================================================
__global__ __launch_bounds__(256) void stats_kernel(const float* __restrict__ Qf,
                                                    const float* __restrict__ Pf) {
    int warp = (blockIdx.x * blockDim.x + threadIdx.x) >> 5;
    int lane = threadIdx.x & 31;
    if (warp >= QN + KN) return;

    const float* row;
    if (warp < QN) row = Qf + (size_t)warp * DN;
    else           row = Pf + (size_t)(warp - QN) * DN;

    float s2 = 0.f, s1 = 0.f;
    #pragma unroll 4
    for (int d = lane * 4; d < DN; d += 32 * 4) {
        float4 v = *(const float4*)(row + d);
        s2 += v.x * v.x + v.y * v.y + v.z * v.z + v.w * v.w;
        s1 += v.x + v.y + v.z + v.w;
    }
    #pragma unroll
    for (int o = 16; o > 0; o >>= 1) {
        s2 += __shfl_xor_sync(0xFFFFFFFFu, s2, o);
        s1 += __shfl_xor_sync(0xFFFFFFFFu, s1, o);
    }
    if (lane == 0) {
        if (warp < QN) { g_qsq[warp] = s2; g_qsum[warp] = s1; }
        else           { g_psq[warp - QN] = s2; g_psum[warp - QN] = s1; }
    }
}

// ============================================================
// 2) Tiled fp32 GEMM (Q @ P^T) with fused distance/exp epilogue.
//    grid = (KN/BN, QN/BM), block = 256 (16x16 threads, 8x8 microtile)
//    Register-staged prefetch of the next K-tile hides global latency
//    behind the FFMA loop. Writes unnormalized u to out_post and
//    deterministic per-tile partials to g_{S,U,M}part.
// ============================================================
__global__ __launch_bounds__(256) void gemm_epi_kernel(const float* __restrict__ Qf,
                                                       const float* __restrict__ Pf,
                                                       float* __restrict__ out_post) {
    __shared__ float Qs[BK][BM + 4];
    __shared__ float Ps[BK][BN + 4];

    const int bx = blockIdx.x;          // column tile (prototypes)
    const int by = blockIdx.y;          // row tile (queries)
    const int tid = threadIdx.x;
    const int tx = tid & 15;            // 0..15 -> 8 cols each
    const int ty = tid >> 4;            // 0..15 -> 8 rows each

    const float* Qb = Qf + (size_t)by * BM * DN;
    const float* Pb = Pf + (size_t)bx * BN * DN;

    // per-thread load coordinates (2 rows of each 128x16 tile per thread)
    int lr[2], lc[2];
    #pragma unroll
    for (int i = 0; i < 2; i++) {
        int idx = tid + i * 256;        // 0..511
        lr[i] = idx >> 2;               // row 0..127
        lc[i] = (idx & 3) * 4;          // k-offset 0,4,8,12
    }

    float acc[8][8];
    #pragma unroll
    for (int r = 0; r < 8; r++)
        #pragma unroll
        for (int c = 0; c < 8; c++) acc[r][c] = 0.f;

    // prefetch first tile into registers
    float4 fq[2], fp[2];
    #pragma unroll
    for (int i = 0; i < 2; i++) {
        fq[i] = *(const float4*)(Qb + (size_t)lr[i] * DN + lc[i]);
        fp[i] = *(const float4*)(Pb + (size_t)lr[i] * DN + lc[i]);
    }

    for (int kt = 0; kt < DN; kt += BK) {
        // commit prefetched registers to shared (transposed [k][row])
        #pragma unroll
        for (int i = 0; i < 2; i++) {
            Qs[lc[i] + 0][lr[i]] = fq[i].x; Qs[lc[i] + 1][lr[i]] = fq[i].y;
            Qs[lc[i] + 2][lr[i]] = fq[i].z; Qs[lc[i] + 3][lr[i]] = fq[i].w;
            Ps[lc[i] + 0][lr[i]] = fp[i].x; Ps[lc[i] + 1][lr[i]] = fp[i].y;
            Ps[lc[i] + 2][lr[i]] = fp[i].z; Ps[lc[i] + 3][lr[i]] = fp[i].w;
        }
        __syncthreads();

        // issue next tile's global loads BEFORE the compute body
        const int ktn = kt + BK;
        if (ktn < DN) {
            #pragma unroll
            for (int i = 0; i < 2; i++) {
                fq[i] = *(const float4*)(Qb + (size_t)lr[i] * DN + ktn + lc[i]);
                fp[i] = *(const float4*)(Pb + (size_t)lr[i] * DN + ktn + lc[i]);
            }
        }

        #pragma unroll
        for (int kk = 0; kk < BK; kk++) {
            float a[8], b[8];
            #pragma unroll
            for (int r = 0; r < 8; r++) a[r] = Qs[kk][ty * 8 + r];
            #pragma unroll
            for (int c = 0; c < 8; c++) b[c] = Ps[kk][tx * 8 + c];
            #pragma unroll
            for (int r = 0; r < 8; r++)
                #pragma unroll
                for (int c = 0; c < 8; c++)
                    acc[r][c] = fmaf(a[r], b[c], acc[r][c]);
        }
        __syncthreads();
    }

    // ---------- fused epilogue ----------
    const int row0 = by * BM + ty * 8;
    const int col0 = bx * BN + tx * 8;
    const float kconst = (float)DN * EPSF * EPSF;

    float psq[8], psm[8];
    #pragma unroll
    for (int c = 0; c < 8; c++) { psq[c] = g_psq[col0 + c]; psm[c] = g_psum[col0 + c]; }

    #pragma unroll
    for (int r = 0; r < 8; r++) {
        const int grow = row0 + r;
        const float qsq = g_qsq[grow];
        const float qsm = g_qsum[grow];

        float su = 0.f, sud = 0.f, mu = 0.f;
        float uv[8];
        #pragma unroll
        for (int c = 0; c < 8; c++) {
            float sq = qsq + psq[c] - 2.f * acc[r][c]
                     + 2.f * EPSF * (qsm - psm[c]) + kconst;
            float dist = sqrtf(fmaxf(sq, 0.f));
            float u = __expf(-dist);
            uv[c] = u;
            su += u;
            sud = fmaf(u, dist, sud);
            mu = fmaxf(mu, u);
        }
        // vector stores of unnormalized u
        float* op = out_post + (size_t)grow * KN + col0;
        *(float4*)(op + 0) = make_float4(uv[0], uv[1], uv[2], uv[3]);
        *(float4*)(op + 4) = make_float4(uv[4], uv[5], uv[6], uv[7]);

        // reduce across the 16 tx lanes sharing this row (lanes 0..15 / 16..31)
        #pragma unroll
        for (int o = 8; o > 0; o >>= 1) {
            su  += __shfl_xor_sync(0xFFFFFFFFu, su,  o);
            sud += __shfl_xor_sync(0xFFFFFFFFu, sud, o);
            mu   = fmaxf(mu, __shfl_xor_sync(0xFFFFFFFFu, mu, o));
        }
        if (tx == 0) {
            g_Spart[(size_t)grow * NCT + bx] = su;
            g_Upart[(size_t)grow * NCT + bx] = sud;
            g_Mpart[(size_t)grow * NCT + bx] = mu;
        }
    }
}

// ============================================================
// 3) Finalize: one block per query row. Deterministic fixed-order
//    reduction of the 8 partials, normalize post, write c and h.
// ============================================================
__global__ __launch_bounds__(256) void finalize_kernel(float* __restrict__ out) {
    const int row = blockIdx.x;

    float S = 0.f, U = 0.f, Mx = 0.f;
    #pragma unroll
    for (int j = 0; j < NCT; j++) {
        S += g_Spart[(size_t)row * NCT + j];
        U += g_Upart[(size_t)row * NCT + j];
        Mx = fmaxf(Mx, g_Mpart[(size_t)row * NCT + j]);
    }
    const float invS = 1.f / S;

    float4* post4 = (float4*)(out + (size_t)row * KN);
    // KN/4 = 256 float4 -> one per thread
    int k = threadIdx.x;
    float4 v = post4[k];
    v.x *= invS; v.y *= invS; v.z *= invS; v.w *= invS;
    post4[k] = v;

    if (threadIdx.x == 0) {
        out[(size_t)QN * KN + row]      = Mx * invS;           // c
        out[(size_t)QN * KN + QN + row] = U * invS + logf(S);  // h
    }
}

// ============================================================
extern "C" void kernel_launch(void* const* d_in, const int* in_sizes, int n_in,
                              void* d_out, int out_size) {
    const float* P  = (const float*)d_in[0];   // class_prototypes [KN, DN]
    const float* Qf = (const float*)d_in[1];   // query_features   [QN, DN]
    float* out = (float*)d_out;                // [QN*KN post | QN c | QN h]

    // 1) row stats: (QN+KN) warps
    {
        int warps = QN + KN;
        int blocks = (warps * 32 + 255) / 256;
        stats_kernel<<<blocks, 256>>>(Qf, P);
    }
    // 2) GEMM + fused epilogue
    {
        dim3 grid(KN / BN, QN / BM);
        gemm_epi_kernel<<<grid, 256>>>(Qf, P, out);
    }
    // 3) finalize
    finalize_kernel<<<QN, 256>>>(out);
}

// round 12
// speedup vs baseline: 2.0348x; 2.0348x over previous
#include <cuda_runtime.h>
#include <cuda_bf16.h>
#include <math.h>
#include <stdint.h>

// Problem shape
#define QN 8192
#define KN 1024
#define DN 1024
#define EPSF 1e-6f

// Tiling
#define BM 128
#define BN 128
#define BKC 32                  // bf16 k-elems per chunk
#define NCH (DN / BKC)          // 32 chunks
#define NPART 16                // 8 col tiles * 2 warp_n halves

// SMEM tile geometry: 128 rows x 32 bf16 (64B) padded to 80B stride
#define TSTRIDE 80
#define TILE_B (128 * TSTRIDE)          // 10240
#define STAGE_B (4 * TILE_B)            // 40960 (Ah, Al, Bh, Bl)
#define SM_QSQ 0
#define SM_QSM 512
#define SM_PSQ 1024
#define SM_PSM 1536
#define SM_TILES 2048
#define SMEM_TOTAL (SM_TILES + 2 * STAGE_B)   // 83968

// ---- allocation-free scratch ----
__device__ unsigned short g_Qhi[(size_t)QN * DN];
__device__ unsigned short g_Qlo[(size_t)QN * DN];
__device__ unsigned short g_Phi[(size_t)KN * DN];
__device__ unsigned short g_Plo[(size_t)KN * DN];
__device__ float g_qsq[QN];
__device__ float g_qsum[QN];
__device__ float g_psq[KN];
__device__ float g_psum[KN];
__device__ float g_Spart[(size_t)QN * NPART];
__device__ float g_Upart[(size_t)QN * NPART];
__device__ float g_Mpart[(size_t)QN * NPART];

// ---- PTX helpers (sm_80+ baseline instructions only; no tcgen05) ----
__device__ __forceinline__ uint32_t smem_to_u32(const void* p) {
    uint32_t a;
    asm("{ .reg .u64 t; cvta.to.shared.u64 t, %1; cvt.u32.u64 %0, t; }" : "=r"(a) : "l"(p));
    return a;
}
__device__ __forceinline__ void cp16(uint32_t dst, const void* src) {
    asm volatile("cp.async.ca.shared.global [%0], [%1], 16;" :: "r"(dst), "l"(src));
}
#define CP_COMMIT() asm volatile("cp.async.commit_group;" ::: "memory")
#define CP_WAIT(n)  asm volatile("cp.async.wait_group %0;" :: "n"(n) : "memory")

__device__ __forceinline__ void ldm_x4(uint32_t* r, uint32_t addr) {
    asm volatile("ldmatrix.sync.aligned.m8n8.x4.shared.b16 {%0,%1,%2,%3}, [%4];"
        : "=r"(r[0]), "=r"(r[1]), "=r"(r[2]), "=r"(r[3]) : "r"(addr));
}
__device__ __forceinline__ void mma16816(float* d, const uint32_t* a, uint32_t b0, uint32_t b1) {
    asm volatile("mma.sync.aligned.m16n8k16.row.col.f32.bf16.bf16.f32 "
        "{%0,%1,%2,%3}, {%4,%5,%6,%7}, {%8,%9}, {%0,%1,%2,%3};"
        : "+f"(d[0]), "+f"(d[1]), "+f"(d[2]), "+f"(d[3])
        : "r"(a[0]), "r"(a[1]), "r"(a[2]), "r"(a[3]), "r"(b0), "r"(b1));
}

// ============================================================
// 1) Convert fp32 -> bf16 hi/lo AND row stats. One warp per row.
// ============================================================
__global__ __launch_bounds__(256) void convert_stats_kernel(const float* __restrict__ Qf,
                                                            const float* __restrict__ Pf) {
    int warp = (blockIdx.x * blockDim.x + threadIdx.x) >> 5;
    int lane = threadIdx.x & 31;
    if (warp >= QN + KN) return;

    bool isQ = warp < QN;
    size_t roff = (size_t)(isQ ? warp : warp - QN) * DN;
    const float* src = (isQ ? Qf : Pf) + roff;
    unsigned short* hi = (isQ ? g_Qhi : g_Phi) + roff;
    unsigned short* lo = (isQ ? g_Qlo : g_Plo) + roff;

    float s1 = 0.f, s2 = 0.f;
    #pragma unroll
    for (int it = 0; it < DN / 128; it++) {
        int d = it * 128 + lane * 4;
        float4 v = *(const float4*)(src + d);
        s2 += v.x * v.x + v.y * v.y + v.z * v.z + v.w * v.w;
        s1 += v.x + v.y + v.z + v.w;

        __nv_bfloat16 h0 = __float2bfloat16(v.x), h1 = __float2bfloat16(v.y);
        __nv_bfloat16 h2 = __float2bfloat16(v.z), h3 = __float2bfloat16(v.w);
        __nv_bfloat16 l0 = __float2bfloat16(v.x - __bfloat162float(h0));
        __nv_bfloat16 l1 = __float2bfloat16(v.y - __bfloat162float(h1));
        __nv_bfloat16 l2 = __float2bfloat16(v.z - __bfloat162float(h2));
        __nv_bfloat16 l3 = __float2bfloat16(v.w - __bfloat162float(h3));

        uint2 hp, lp;
        hp.x = (uint32_t)__bfloat16_as_ushort(h0) | ((uint32_t)__bfloat16_as_ushort(h1) << 16);
        hp.y = (uint32_t)__bfloat16_as_ushort(h2) | ((uint32_t)__bfloat16_as_ushort(h3) << 16);
        lp.x = (uint32_t)__bfloat16_as_ushort(l0) | ((uint32_t)__bfloat16_as_ushort(l1) << 16);
        lp.y = (uint32_t)__bfloat16_as_ushort(l2) | ((uint32_t)__bfloat16_as_ushort(l3) << 16);
        *(uint2*)(hi + d) = hp;
        *(uint2*)(lo + d) = lp;
    }
    #pragma unroll
    for (int o = 16; o > 0; o >>= 1) {
        s2 += __shfl_xor_sync(0xFFFFFFFFu, s2, o);
        s1 += __shfl_xor_sync(0xFFFFFFFFu, s1, o);
    }
    if (lane == 0) {
        if (isQ) { g_qsq[warp] = s2; g_qsum[warp] = s1; }
        else     { g_psq[warp - QN] = s2; g_psum[warp - QN] = s1; }
    }
}

// load one 128x32 bf16 tile (chunk ch) into padded SMEM via cp.async
__device__ __forceinline__ void load_tile(uint32_t dst_base, const unsigned short* src,
                                          int ch, int tid) {
    #pragma unroll
    for (int ii = 0; ii < 2; ii++) {
        int j = tid + ii * 256;         // 0..511
        int row = j >> 2, c = j & 3;    // 4 x 16B per row
        cp16(dst_base + row * TSTRIDE + c * 16,
             src + (size_t)row * DN + ch * BKC + c * 8);
    }
}

// ============================================================
// 2) bf16-split GEMM via mma.sync (HMMA) + fused dist/exp epilogue.
//    grid=(KN/BN, QN/BM), 256 threads (8 warps, 4x2), cp.async 2-stage.
// ============================================================
__global__ void __launch_bounds__(256, 1) tc_gemm_kernel(float* __restrict__ out) {
    extern __shared__ char smem[];
    const int bx = blockIdx.x, by = blockIdx.y;
    const int tid = threadIdx.x;
    const int wid = tid >> 5, lane = tid & 31;
    const int warp_m = wid & 3;         // 32-row band
    const int warp_n = wid >> 2;        // 64-col half
    const uint32_t sb = smem_to_u32(smem);

    if (tid < 128) {
        ((float*)(smem + SM_QSQ))[tid] = g_qsq[by * BM + tid];
        ((float*)(smem + SM_QSM))[tid] = g_qsum[by * BM + tid];
        ((float*)(smem + SM_PSQ))[tid] = g_psq[bx * BN + tid];
        ((float*)(smem + SM_PSM))[tid] = g_psum[bx * BN + tid];
    }

    const unsigned short* Ah = g_Qhi + (size_t)by * BM * DN;
    const unsigned short* Al = g_Qlo + (size_t)by * BM * DN;
    const unsigned short* Bh = g_Phi + (size_t)bx * BN * DN;
    const unsigned short* Bl = g_Plo + (size_t)bx * BN * DN;

    // prologue: chunks 0,1 into stages 0,1
    {
        uint32_t b0 = sb + SM_TILES;
        load_tile(b0 + 0 * TILE_B, Ah, 0, tid);
        load_tile(b0 + 1 * TILE_B, Al, 0, tid);
        load_tile(b0 + 2 * TILE_B, Bh, 0, tid);
        load_tile(b0 + 3 * TILE_B, Bl, 0, tid);
        CP_COMMIT();
        uint32_t b1 = sb + SM_TILES + STAGE_B;
        load_tile(b1 + 0 * TILE_B, Ah, 1, tid);
        load_tile(b1 + 1 * TILE_B, Al, 1, tid);
        load_tile(b1 + 2 * TILE_B, Bh, 1, tid);
        load_tile(b1 + 3 * TILE_B, Bl, 1, tid);
        CP_COMMIT();
    }

    float acc[2][8][4];
    #pragma unroll
    for (int t = 0; t < 2; t++)
        #pragma unroll
        for (int u = 0; u < 8; u++)
            #pragma unroll
            for (int v = 0; v < 4; v++) acc[t][u][v] = 0.f;

    for (int ch = 0; ch < NCH; ch++) {
        if (ch + 1 < NCH) { CP_WAIT(1); } else { CP_WAIT(0); }
        __syncthreads();

        const uint32_t base = sb + SM_TILES + (ch & 1) * STAGE_B;
        // per-lane ldmatrix addressing offsets
        const uint32_t arow = warp_m * 32 + (lane & 15);
        const uint32_t brow = warp_n * 64 + (lane & 15);
        const uint32_t khalf = (lane >> 4) * 16;     // byte offset of k half

        #pragma unroll
        for (int s = 0; s < 2; s++) {                // two k16 steps per chunk
            const uint32_t koff = s * 32 + khalf;
            uint32_t ah[2][4], al[2][4], bh[4][4], bl[4][4];
            #pragma unroll
            for (int t = 0; t < 2; t++) {
                ldm_x4(ah[t], base + 0 * TILE_B + (arow + t * 16) * TSTRIDE + koff);
                ldm_x4(al[t], base + 1 * TILE_B + (arow + t * 16) * TSTRIDE + koff);
            }
            #pragma unroll
            for (int p = 0; p < 4; p++) {
                ldm_x4(bh[p], base + 2 * TILE_B + (brow + p * 16) * TSTRIDE + koff);
                ldm_x4(bl[p], base + 3 * TILE_B + (brow + p * 16) * TSTRIDE + koff);
            }
            #pragma unroll
            for (int t = 0; t < 2; t++) {
                #pragma unroll
                for (int u = 0; u < 8; u++) {
                    const int p = u >> 1, q = u & 1;
                    mma16816(acc[t][u], ah[t], bh[p][q], bh[p][2 + q]);   // hi*hi
                    mma16816(acc[t][u], ah[t], bl[p][q], bl[p][2 + q]);   // hi*lo
                    mma16816(acc[t][u], al[t], bh[p][q], bh[p][2 + q]);   // lo*hi
                }
            }
        }
        __syncthreads();    // all warps done reading before overwrite
        if (ch + 2 < NCH) {
            const uint32_t nb = sb + SM_TILES + (ch & 1) * STAGE_B;
            load_tile(nb + 0 * TILE_B, Ah, ch + 2, tid);
            load_tile(nb + 1 * TILE_B, Al, ch + 2, tid);
            load_tile(nb + 2 * TILE_B, Bh, ch + 2, tid);
            load_tile(nb + 3 * TILE_B, Bl, ch + 2, tid);
            CP_COMMIT();
        }
    }

    // ---------- fused epilogue ----------
    const float kconst = (float)DN * EPSF * EPSF;
    const float* sQSQ = (const float*)(smem + SM_QSQ);
    const float* sQSM = (const float*)(smem + SM_QSM);
    const float* sPSQ = (const float*)(smem + SM_PSQ);
    const float* sPSM = (const float*)(smem + SM_PSM);

    #pragma unroll
    for (int t = 0; t < 2; t++) {
        #pragma unroll
        for (int rr = 0; rr < 2; rr++) {
            const int rowl = warp_m * 32 + t * 16 + rr * 8 + (lane >> 2);
            const int grow = by * BM + rowl;
            const float qsq = sQSQ[rowl];
            const float qsm = sQSM[rowl];
            float su = 0.f, sud = 0.f, mu = 0.f;
            float* op = out + (size_t)grow * KN + bx * BN + warp_n * 64;
            #pragma unroll
            for (int u = 0; u < 8; u++) {
                const int c0 = u * 8 + (lane & 3) * 2;
                const float cr0 = acc[t][u][rr * 2 + 0];
                const float cr1 = acc[t][u][rr * 2 + 1];
                const int gc0 = warp_n * 64 + c0;
                float sq0 = qsq + sPSQ[gc0]     - 2.f * cr0 + 2.f * EPSF * (qsm - sPSM[gc0])     + kconst;
                float sq1 = qsq + sPSQ[gc0 + 1] - 2.f * cr1 + 2.f * EPSF * (qsm - sPSM[gc0 + 1]) + kconst;
                float d0 = sqrtf(fmaxf(sq0, 0.f));
                float d1 = sqrtf(fmaxf(sq1, 0.f));
                float u0 = __expf(-d0);
                float u1 = __expf(-d1);
                su += u0 + u1;
                sud = fmaf(u0, d0, fmaf(u1, d1, sud));
                mu = fmaxf(mu, fmaxf(u0, u1));
                *(float2*)(op + c0) = make_float2(u0, u1);
            }
            // reduce across the 4 lanes of the quad (same row)
            #pragma unroll
            for (int o = 1; o <= 2; o <<= 1) {
                su  += __shfl_xor_sync(0xFFFFFFFFu, su,  o);
                sud += __shfl_xor_sync(0xFFFFFFFFu, sud, o);
                mu   = fmaxf(mu, __shfl_xor_sync(0xFFFFFFFFu, mu, o));
            }
            if ((lane & 3) == 0) {
                const size_t pidx = (size_t)grow * NPART + bx * 2 + warp_n;
                g_Spart[pidx] = su;
                g_Upart[pidx] = sud;
                g_Mpart[pidx] = mu;
            }
        }
    }
}

// ============================================================
// 3) Finalize: one block per query row, fixed-order reduction.
// ============================================================
__global__ __launch_bounds__(256) void finalize_kernel(float* __restrict__ out) {
    const int row = blockIdx.x;
    float S = 0.f, U = 0.f, Mx = 0.f;
    #pragma unroll
    for (int j = 0; j < NPART; j++) {
        S += g_Spart[(size_t)row * NPART + j];
        U += g_Upart[(size_t)row * NPART + j];
        Mx = fmaxf(Mx, g_Mpart[(size_t)row * NPART + j]);
    }
    const float invS = 1.f / S;

    float4* post4 = (float4*)(out + (size_t)row * KN);
    float4 v = post4[threadIdx.x];
    v.x *= invS; v.y *= invS; v.z *= invS; v.w *= invS;
    post4[threadIdx.x] = v;

    if (threadIdx.x == 0) {
        out[(size_t)QN * KN + row]      = Mx * invS;           // c
        out[(size_t)QN * KN + QN + row] = U * invS + logf(S);  // h
    }
}

// ============================================================
extern "C" void kernel_launch(void* const* d_in, const int* in_sizes, int n_in,
                              void* d_out, int out_size) {
    const float* P  = (const float*)d_in[0];   // class_prototypes [KN, DN]
    const float* Qf = (const float*)d_in[1];   // query_features   [QN, DN]
    float* out = (float*)d_out;

    {
        int blocks = ((QN + KN) * 32 + 255) / 256;
        convert_stats_kernel<<<blocks, 256>>>(Qf, P);
    }
    cudaFuncSetAttribute(tc_gemm_kernel, cudaFuncAttributeMaxDynamicSharedMemorySize, SMEM_TOTAL);
    {
        dim3 grid(KN / BN, QN / BM);
        tc_gemm_kernel<<<grid, 256, SMEM_TOTAL>>>(out);
    }
    finalize_kernel<<<QN, 256>>>(out);
}

// round 13
// speedup vs baseline: 2.2175x; 1.0898x over previous
#include <cuda_runtime.h>
#include <cuda_bf16.h>
#include <math.h>
#include <stdint.h>

// Problem shape
#define QN 8192
#define KN 1024
#define DN 1024
#define EPSF 1e-6f

// Tiling
#define BM 128
#define BN 128
#define BKC 32                  // bf16 k-elems per chunk
#define NCH (DN / BKC)          // 32 chunks
#define NPART 16                // 8 col tiles * 2 warp_n halves

// SMEM tile geometry: 128 rows x 32 bf16 (64B) padded to 80B stride
#define TSTRIDE 80
#define TILE_B (128 * TSTRIDE)          // 10240
#define STAGE_B (4 * TILE_B)            // 40960 (Ah, Al, Bh, Bl)
#define SM_QSQ 0
#define SM_QSM 512
#define SM_PSQ 1024
#define SM_PSM 1536
#define SM_TILES 2048
#define SMEM_TOTAL (SM_TILES + 2 * STAGE_B)   // 83968 -> 2 CTAs/SM fits 228KB

// ---- allocation-free scratch ----
__device__ unsigned short g_Qhi[(size_t)QN * DN];
__device__ unsigned short g_Qlo[(size_t)QN * DN];
__device__ unsigned short g_Phi[(size_t)KN * DN];
__device__ unsigned short g_Plo[(size_t)KN * DN];
__device__ float g_qsq[QN];
__device__ float g_qsum[QN];
__device__ float g_psq[KN];
__device__ float g_psum[KN];
__device__ float g_Spart[(size_t)QN * NPART];
__device__ float g_Upart[(size_t)QN * NPART];
__device__ float g_Mpart[(size_t)QN * NPART];

// ---- PTX helpers ----
__device__ __forceinline__ uint32_t smem_to_u32(const void* p) {
    uint32_t a;
    asm("{ .reg .u64 t; cvta.to.shared.u64 t, %1; cvt.u32.u64 %0, t; }" : "=r"(a) : "l"(p));
    return a;
}
__device__ __forceinline__ void cp16(uint32_t dst, const void* src) {
    asm volatile("cp.async.ca.shared.global [%0], [%1], 16;" :: "r"(dst), "l"(src));
}
#define CP_COMMIT() asm volatile("cp.async.commit_group;" ::: "memory")
#define CP_WAIT(n)  asm volatile("cp.async.wait_group %0;" :: "n"(n) : "memory")

__device__ __forceinline__ void ldm_x4(uint32_t* r, uint32_t addr) {
    asm volatile("ldmatrix.sync.aligned.m8n8.x4.shared.b16 {%0,%1,%2,%3}, [%4];"
        : "=r"(r[0]), "=r"(r[1]), "=r"(r[2]), "=r"(r[3]) : "r"(addr));
}
__device__ __forceinline__ void mma16816(float* d, const uint32_t* a, uint32_t b0, uint32_t b1) {
    asm volatile("mma.sync.aligned.m16n8k16.row.col.f32.bf16.bf16.f32 "
        "{%0,%1,%2,%3}, {%4,%5,%6,%7}, {%8,%9}, {%0,%1,%2,%3};"
        : "+f"(d[0]), "+f"(d[1]), "+f"(d[2]), "+f"(d[3])
        : "r"(a[0]), "r"(a[1]), "r"(a[2]), "r"(a[3]), "r"(b0), "r"(b1));
}

// ============================================================
// 1) Convert fp32 -> bf16 hi/lo AND row stats. One warp per row.
// ============================================================
__global__ __launch_bounds__(256) void convert_stats_kernel(const float* __restrict__ Qf,
                                                            const float* __restrict__ Pf) {
    int warp = (blockIdx.x * blockDim.x + threadIdx.x) >> 5;
    int lane = threadIdx.x & 31;
    if (warp >= QN + KN) return;

    bool isQ = warp < QN;
    size_t roff = (size_t)(isQ ? warp : warp - QN) * DN;
    const float* src = (isQ ? Qf : Pf) + roff;
    unsigned short* hi = (isQ ? g_Qhi : g_Phi) + roff;
    unsigned short* lo = (isQ ? g_Qlo : g_Plo) + roff;

    float s1 = 0.f, s2 = 0.f;
    #pragma unroll
    for (int it = 0; it < DN / 128; it++) {
        int d = it * 128 + lane * 4;
        float4 v = *(const float4*)(src + d);
        s2 += v.x * v.x + v.y * v.y + v.z * v.z + v.w * v.w;
        s1 += v.x + v.y + v.z + v.w;

        __nv_bfloat16 h0 = __float2bfloat16(v.x), h1 = __float2bfloat16(v.y);
        __nv_bfloat16 h2 = __float2bfloat16(v.z), h3 = __float2bfloat16(v.w);
        __nv_bfloat16 l0 = __float2bfloat16(v.x - __bfloat162float(h0));
        __nv_bfloat16 l1 = __float2bfloat16(v.y - __bfloat162float(h1));
        __nv_bfloat16 l2 = __float2bfloat16(v.z - __bfloat162float(h2));
        __nv_bfloat16 l3 = __float2bfloat16(v.w - __bfloat162float(h3));

        uint2 hp, lp;
        hp.x = (uint32_t)__bfloat16_as_ushort(h0) | ((uint32_t)__bfloat16_as_ushort(h1) << 16);
        hp.y = (uint32_t)__bfloat16_as_ushort(h2) | ((uint32_t)__bfloat16_as_ushort(h3) << 16);
        lp.x = (uint32_t)__bfloat16_as_ushort(l0) | ((uint32_t)__bfloat16_as_ushort(l1) << 16);
        lp.y = (uint32_t)__bfloat16_as_ushort(l2) | ((uint32_t)__bfloat16_as_ushort(l3) << 16);
        *(uint2*)(hi + d) = hp;
        *(uint2*)(lo + d) = lp;
    }
    #pragma unroll
    for (int o = 16; o > 0; o >>= 1) {
        s2 += __shfl_xor_sync(0xFFFFFFFFu, s2, o);
        s1 += __shfl_xor_sync(0xFFFFFFFFu, s1, o);
    }
    if (lane == 0) {
        if (isQ) { g_qsq[warp] = s2; g_qsum[warp] = s1; }
        else     { g_psq[warp - QN] = s2; g_psum[warp - QN] = s1; }
    }
}

// load one 128x32 bf16 tile (chunk ch) into padded SMEM via cp.async
__device__ __forceinline__ void load_tile(uint32_t dst_base, const unsigned short* src,
                                          int ch, int tid) {
    #pragma unroll
    for (int ii = 0; ii < 2; ii++) {
        int j = tid + ii * 256;         // 0..511
        int row = j >> 2, c = j & 3;    // 4 x 16B per row
        cp16(dst_base + row * TSTRIDE + c * 16,
             src + (size_t)row * DN + ch * BKC + c * 8);
    }
}

// ============================================================
// 2) bf16-split GEMM via mma.sync + fused dist/exp epilogue.
//    grid=(KN/BN, QN/BM), 256 threads (8 warps, 4x2), cp.async 2-stage,
//    2 CTAs/SM (registers capped at 128 via n-half fragment scheduling).
// ============================================================
__global__ void __launch_bounds__(256, 2) tc_gemm_kernel(float* __restrict__ out) {
    extern __shared__ char smem[];
    const int bx = blockIdx.x, by = blockIdx.y;
    const int tid = threadIdx.x;
    const int wid = tid >> 5, lane = tid & 31;
    const int warp_m = wid & 3;         // 32-row band
    const int warp_n = wid >> 2;        // 64-col half
    const uint32_t sb = smem_to_u32(smem);

    if (tid < 128) {
        ((float*)(smem + SM_QSQ))[tid] = g_qsq[by * BM + tid];
        ((float*)(smem + SM_QSM))[tid] = g_qsum[by * BM + tid];
        ((float*)(smem + SM_PSQ))[tid] = g_psq[bx * BN + tid];
        ((float*)(smem + SM_PSM))[tid] = g_psum[bx * BN + tid];
    }

    const unsigned short* Ah = g_Qhi + (size_t)by * BM * DN;
    const unsigned short* Al = g_Qlo + (size_t)by * BM * DN;
    const unsigned short* Bh = g_Phi + (size_t)bx * BN * DN;
    const unsigned short* Bl = g_Plo + (size_t)bx * BN * DN;

    // prologue: chunks 0,1 into stages 0,1
    {
        uint32_t b0 = sb + SM_TILES;
        load_tile(b0 + 0 * TILE_B, Ah, 0, tid);
        load_tile(b0 + 1 * TILE_B, Al, 0, tid);
        load_tile(b0 + 2 * TILE_B, Bh, 0, tid);
        load_tile(b0 + 3 * TILE_B, Bl, 0, tid);
        CP_COMMIT();
        uint32_t b1 = sb + SM_TILES + STAGE_B;
        load_tile(b1 + 0 * TILE_B, Ah, 1, tid);
        load_tile(b1 + 1 * TILE_B, Al, 1, tid);
        load_tile(b1 + 2 * TILE_B, Bh, 1, tid);
        load_tile(b1 + 3 * TILE_B, Bl, 1, tid);
        CP_COMMIT();
    }

    float acc[2][8][4];
    #pragma unroll
    for (int t = 0; t < 2; t++)
        #pragma unroll
        for (int u = 0; u < 8; u++)
            #pragma unroll
            for (int v = 0; v < 4; v++) acc[t][u][v] = 0.f;

    for (int ch = 0; ch < NCH; ch++) {
        if (ch + 1 < NCH) { CP_WAIT(1); } else { CP_WAIT(0); }
        __syncthreads();

        const uint32_t base = sb + SM_TILES + (ch & 1) * STAGE_B;
        const uint32_t arow = warp_m * 32 + (lane & 15);
        const uint32_t brow = warp_n * 64 + (lane & 15);
        const uint32_t khalf = (lane >> 4) * 16;     // byte offset of k half

        #pragma unroll
        for (int s = 0; s < 2; s++) {                // two k16 steps per chunk
            const uint32_t koff = s * 32 + khalf;
            uint32_t ah[2][4], al[2][4];
            #pragma unroll
            for (int t = 0; t < 2; t++) {
                ldm_x4(ah[t], base + 0 * TILE_B + (arow + t * 16) * TSTRIDE + koff);
                ldm_x4(al[t], base + 1 * TILE_B + (arow + t * 16) * TSTRIDE + koff);
            }
            #pragma unroll
            for (int nh = 0; nh < 2; nh++) {         // n-halves: keeps live B frags at 16 regs
                uint32_t bh[2][4], bl[2][4];
                #pragma unroll
                for (int pp = 0; pp < 2; pp++) {
                    const int p = nh * 2 + pp;
                    ldm_x4(bh[pp], base + 2 * TILE_B + (brow + p * 16) * TSTRIDE + koff);
                    ldm_x4(bl[pp], base + 3 * TILE_B + (brow + p * 16) * TSTRIDE + koff);
                }
                #pragma unroll
                for (int t = 0; t < 2; t++) {
                    #pragma unroll
                    for (int pp = 0; pp < 2; pp++) {
                        #pragma unroll
                        for (int q = 0; q < 2; q++) {
                            const int u = (nh * 2 + pp) * 2 + q;
                            mma16816(acc[t][u], ah[t], bh[pp][q], bh[pp][2 + q]);   // hi*hi
                            mma16816(acc[t][u], ah[t], bl[pp][q], bl[pp][2 + q]);   // hi*lo
                            mma16816(acc[t][u], al[t], bh[pp][q], bh[pp][2 + q]);   // lo*hi
                        }
                    }
                }
            }
        }
        __syncthreads();    // all warps done reading before overwrite
        if (ch + 2 < NCH) {
            const uint32_t nb = sb + SM_TILES + (ch & 1) * STAGE_B;
            load_tile(nb + 0 * TILE_B, Ah, ch + 2, tid);
            load_tile(nb + 1 * TILE_B, Al, ch + 2, tid);
            load_tile(nb + 2 * TILE_B, Bh, ch + 2, tid);
            load_tile(nb + 3 * TILE_B, Bl, ch + 2, tid);
            CP_COMMIT();
        }
    }

    // ---------- fused epilogue ----------
    const float kconst = (float)DN * EPSF * EPSF;
    const float* sQSQ = (const float*)(smem + SM_QSQ);
    const float* sQSM = (const float*)(smem + SM_QSM);
    const float* sPSQ = (const float*)(smem + SM_PSQ);
    const float* sPSM = (const float*)(smem + SM_PSM);

    #pragma unroll
    for (int t = 0; t < 2; t++) {
        #pragma unroll
        for (int rr = 0; rr < 2; rr++) {
            const int rowl = warp_m * 32 + t * 16 + rr * 8 + (lane >> 2);
            const int grow = by * BM + rowl;
            const float qsq = sQSQ[rowl];
            const float qsm = sQSM[rowl];
            float su = 0.f, sud = 0.f, mu = 0.f;
            float* op = out + (size_t)grow * KN + bx * BN + warp_n * 64;
            #pragma unroll
            for (int u = 0; u < 8; u++) {
                const int c0 = u * 8 + (lane & 3) * 2;
                const float cr0 = acc[t][u][rr * 2 + 0];
                const float cr1 = acc[t][u][rr * 2 + 1];
                const int gc0 = warp_n * 64 + c0;
                float sq0 = qsq + sPSQ[gc0]     - 2.f * cr0 + 2.f * EPSF * (qsm - sPSM[gc0])     + kconst;
                float sq1 = qsq + sPSQ[gc0 + 1] - 2.f * cr1 + 2.f * EPSF * (qsm - sPSM[gc0 + 1]) + kconst;
                float d0 = sqrtf(fmaxf(sq0, 0.f));
                float d1 = sqrtf(fmaxf(sq1, 0.f));
                float u0 = __expf(-d0);
                float u1 = __expf(-d1);
                su += u0 + u1;
                sud = fmaf(u0, d0, fmaf(u1, d1, sud));
                mu = fmaxf(mu, fmaxf(u0, u1));
                *(float2*)(op + c0) = make_float2(u0, u1);
            }
            // reduce across the 4 lanes of the quad (same row)
            #pragma unroll
            for (int o = 1; o <= 2; o <<= 1) {
                su  += __shfl_xor_sync(0xFFFFFFFFu, su,  o);
                sud += __shfl_xor_sync(0xFFFFFFFFu, sud, o);
                mu   = fmaxf(mu, __shfl_xor_sync(0xFFFFFFFFu, mu, o));
            }
            if ((lane & 3) == 0) {
                const size_t pidx = (size_t)grow * NPART + bx * 2 + warp_n;
                g_Spart[pidx] = su;
                g_Upart[pidx] = sud;
                g_Mpart[pidx] = mu;
            }
        }
    }
}

// ============================================================
// 3) Finalize: one block per query row, fixed-order reduction.
// ============================================================
__global__ __launch_bounds__(256) void finalize_kernel(float* __restrict__ out) {
    const int row = blockIdx.x;
    float S = 0.f, U = 0.f, Mx = 0.f;
    #pragma unroll
    for (int j = 0; j < NPART; j++) {
        S += g_Spart[(size_t)row * NPART + j];
        U += g_Upart[(size_t)row * NPART + j];
        Mx = fmaxf(Mx, g_Mpart[(size_t)row * NPART + j]);
    }
    const float invS = 1.f / S;

    float4* post4 = (float4*)(out + (size_t)row * KN);
    float4 v = post4[threadIdx.x];
    v.x *= invS; v.y *= invS; v.z *= invS; v.w *= invS;
    post4[threadIdx.x] = v;

    if (threadIdx.x == 0) {
        out[(size_t)QN * KN + row]      = Mx * invS;           // c
        out[(size_t)QN * KN + QN + row] = U * invS + logf(S);  // h
    }
}

// ============================================================
extern "C" void kernel_launch(void* const* d_in, const int* in_sizes, int n_in,
                              void* d_out, int out_size) {
    const float* P  = (const float*)d_in[0];   // class_prototypes [KN, DN]
    const float* Qf = (const float*)d_in[1];   // query_features   [QN, DN]
    float* out = (float*)d_out;

    {
        int blocks = ((QN + KN) * 32 + 255) / 256;
        convert_stats_kernel<<<blocks, 256>>>(Qf, P);
    }
    cudaFuncSetAttribute(tc_gemm_kernel, cudaFuncAttributeMaxDynamicSharedMemorySize, SMEM_TOTAL);
    {
        dim3 grid(KN / BN, QN / BM);
        tc_gemm_kernel<<<grid, 256, SMEM_TOTAL>>>(out);
    }
    finalize_kernel<<<QN, 256>>>(out);
}